// round 7
// baseline (speedup 1.0000x reference)
#include <cuda_runtime.h>
#include <cuda_bf16.h>
#include <cuda_fp16.h>
#include <cstdint>

#define N_NODES_C 100000
#define N_EDGES_C 800000
#define HEADS 4
#define OUT_CH 32
#define IN_CH 128
#define HC 128
#define EPS_F 1e-8f
#define GT 512            // GEMM threads per CTA

// ---------------- device scratch (no allocs allowed) ----------------
__device__ __align__(16) uint32_t g_h16[(size_t)N_NODES_C * 64]; // h as half2 [N][64]
__device__ __align__(16) float g_as[N_NODES_C * HEADS];          // alpha_s -> exp factors
__device__ __align__(16) float g_den[N_NODES_C * HEADS];         // softmax denominators
__device__ __align__(16) int2  g_edges[N_EDGES_C];               // decoded (s,t)
__device__ unsigned int g_maxs;                                  // ordered-encoded max of as
__device__ int g_is64;                                           // edge index dtype flag
__device__ __align__(16) unsigned short g_Whi[HC * 128];         // W bf16 hi, swizzled
__device__ __align__(16) unsigned short g_Wlo[HC * 128];         // W bf16 lo, swizzled

__device__ __forceinline__ unsigned int f2o(float f) {
    unsigned int b = __float_as_uint(f);
    return (b & 0x80000000u) ? ~b : (b | 0x80000000u);
}
__device__ __forceinline__ float o2f(unsigned int u) {
    unsigned int b = (u & 0x80000000u) ? (u ^ 0x80000000u) : ~u;
    return __uint_as_float(b);
}
__device__ __forceinline__ int ldidx(const void* p, long long i, int is64) {
    return is64 ? (int)((const long long*)p)[i] : ((const int*)p)[i];
}
__device__ __forceinline__ void red_v4(float* ptr, float4 v) {
    asm volatile("red.global.add.v4.f32 [%0], {%1,%2,%3,%4};"
                 :: "l"(ptr), "f"(v.x), "f"(v.y), "f"(v.z), "f"(v.w) : "memory");
}
__device__ __forceinline__ uint32_t smem_u32(const void* p) {
    uint32_t a;
    asm("{ .reg .u64 t; cvta.to.shared.u64 t, %1; cvt.u32.u64 %0, t; }" : "=r"(a) : "l"(p));
    return a;
}
__device__ __forceinline__ void cp_async16(uint32_t saddr, const void* gaddr) {
    asm volatile("cp.async.cg.shared.global [%0], [%1], 16;" :: "r"(saddr), "l"(gaddr));
}
__device__ __forceinline__ void ldm_x4(uint32_t* r, uint32_t addr) {
    asm volatile("ldmatrix.sync.aligned.m8n8.x4.shared.b16 {%0,%1,%2,%3}, [%4];"
                 : "=r"(r[0]), "=r"(r[1]), "=r"(r[2]), "=r"(r[3]) : "r"(addr));
}
__device__ __forceinline__ void mma_bf16(float* d, const uint32_t* a, const uint32_t* b) {
    asm volatile(
        "mma.sync.aligned.m16n8k16.row.col.f32.bf16.bf16.f32 "
        "{%0,%1,%2,%3}, {%4,%5,%6,%7}, {%8,%9}, {%0,%1,%2,%3};"
        : "+f"(d[0]), "+f"(d[1]), "+f"(d[2]), "+f"(d[3])
        : "r"(a[0]), "r"(a[1]), "r"(a[2]), "r"(a[3]), "r"(b[0]), "r"(b[1]));
}
// XOR swizzle: row stride 256B (128 bf16)
__device__ __forceinline__ uint32_t swz(int row, int kByte) {
    return (uint32_t)(row * 256 + (kByte ^ ((row & 7) << 4)));
}

// SMEM layout (bytes)
#define SM_BIAS 0
#define SM_ATT  512
#define SM_RED  1536
#define SM_BHI  2048
#define SM_BLO  (SM_BHI + 32768)
#define SM_A    (SM_BLO + 32768)       // two buffers of 65536 (AHI 32KB + ALO 32KB)
#define SM_TOTAL (SM_A + 2 * 65536)    // 198656

// ---------------- prep: W split + dtype detection ----------------
__global__ void prep_kernel(const float* __restrict__ W, const void* __restrict__ idx,
                            int nscan, int nnodes) {
    if (blockIdx.x == 0) {
        __shared__ int bad;
        if (threadIdx.x == 0) bad = 0;
        __syncthreads();
        const long long* p = (const long long*)idx;
        int ok = 1;
        for (int i = threadIdx.x; i < nscan; i += blockDim.x) {
            long long v = p[i];
            if (v < 0 || v >= (long long)nnodes) ok = 0;
        }
        if (!ok) atomicExch(&bad, 1);
        __syncthreads();
        if (threadIdx.x == 0) {
            g_is64 = bad ? 0 : 1;
            g_maxs = 0u;
        }
    }
    for (int idx2 = blockIdx.x * blockDim.x + threadIdx.x; idx2 < HC * IN_CH;
         idx2 += blockDim.x * gridDim.x) {
        int n = idx2 >> 7;
        int k = idx2 & 127;
        float w = W[idx2];
        __nv_bfloat16 hi = __float2bfloat16(w);
        float rem = w - __bfloat162float(hi);
        __nv_bfloat16 lo = __float2bfloat16(rem);
        uint32_t off = swz(n, k * 2) >> 1;
        g_Whi[off] = __bfloat16_as_ushort(hi);
        g_Wlo[off] = __bfloat16_as_ushort(lo);
    }
}

// ---------------- A-tile convert+store helper ----------------
__device__ __forceinline__ void store_a(char* smem, uint32_t bufbase, int g, float4 v) {
    int r = g >> 5;
    int c4 = (g & 31) * 4;
    __nv_bfloat16 h0 = __float2bfloat16(v.x);
    __nv_bfloat16 h1 = __float2bfloat16(v.y);
    __nv_bfloat16 h2 = __float2bfloat16(v.z);
    __nv_bfloat16 h3 = __float2bfloat16(v.w);
    __nv_bfloat16 l0 = __float2bfloat16(v.x - __bfloat162float(h0));
    __nv_bfloat16 l1 = __float2bfloat16(v.y - __bfloat162float(h1));
    __nv_bfloat16 l2 = __float2bfloat16(v.z - __bfloat162float(h2));
    __nv_bfloat16 l3 = __float2bfloat16(v.w - __bfloat162float(h3));
    uint32_t hiA = ((uint32_t)__bfloat16_as_ushort(h1) << 16) | __bfloat16_as_ushort(h0);
    uint32_t hiB = ((uint32_t)__bfloat16_as_ushort(h3) << 16) | __bfloat16_as_ushort(h2);
    uint32_t loA = ((uint32_t)__bfloat16_as_ushort(l1) << 16) | __bfloat16_as_ushort(l0);
    uint32_t loB = ((uint32_t)__bfloat16_as_ushort(l3) << 16) | __bfloat16_as_ushort(l2);
    uint32_t off = swz(r, c4 * 2);
    *(uint2*)(smem + bufbase + off) = make_uint2(hiA, hiB);
    *(uint2*)(smem + bufbase + 32768 + off) = make_uint2(loA, loB);
}

// ---------------- persistent mma.sync GEMM + fused alpha_s epilogue ----------------
// grid = #SMs; 512 threads; 16 warps 4x4; warp tile 32x32; M-tile 128; A double-buffered.
__global__ void __launch_bounds__(GT, 1)
gat_gemm_kernel(const float* __restrict__ X, const float* __restrict__ bias,
                const float* __restrict__ att, int M, int tiles) {
    extern __shared__ char smem[];
    const uint32_t sb = smem_u32(smem);
    const int tid = threadIdx.x, lane = tid & 31, wid = tid >> 5;
    const int wr = wid & 3, wc = wid >> 2;
    const int mrow = wr * 32, ncol = wc * 32;

    if (tid < 128) ((float*)(smem + SM_BIAS))[tid] = bias[tid];
    if (tid < 256) ((float*)(smem + SM_ATT))[tid] = att[tid];

    // W hi/lo (32KB each) once per CTA via cp.async
    {
        const char* wh = (const char*)g_Whi;
        const char* wl = (const char*)g_Wlo;
#pragma unroll
        for (int it = 0; it < 4; it++) {
            int g = (tid + it * GT) * 16;
            cp_async16(sb + SM_BHI + g, wh + g);
            cp_async16(sb + SM_BLO + g, wl + g);
        }
        asm volatile("cp.async.commit_group;");
    }

    // preload first tile into buffer 0
    int t0 = blockIdx.x;
    if (t0 < tiles) {
#pragma unroll
        for (int it = 0; it < 8; it++) {
            int g = tid + it * GT;
            int grow = t0 * 128 + (g >> 5);
            float4 v = make_float4(0.f, 0.f, 0.f, 0.f);
            if (grow < M) v = __ldg((const float4*)(X + (size_t)grow * IN_CH + (g & 31) * 4));
            store_a(smem, SM_A, g, v);
        }
    }
    asm volatile("cp.async.wait_group 0;" ::: "memory");
    __syncthreads();

    const int a_row = (lane & 15);
    const int a_koff = (lane >> 4) * 8;
    const int b_nr = (lane & 7) + ((lane >> 4) & 1) * 8;
    const int b_koff = ((lane >> 3) & 1) * 8;
    const float* s_bias = (const float*)(smem + SM_BIAS);
    const float* s_att = (const float*)(smem + SM_ATT);
    const int q = lane & 3, rg = lane >> 2;

    float lmax = -3.4e38f;
    int buf = 0;

    for (int t = t0; t < tiles; t += gridDim.x) {
        const int tn = t + gridDim.x;
        // prefetch next X tile into registers (hides DRAM latency under MMA)
        float4 xr[8];
        if (tn < tiles) {
#pragma unroll
            for (int it = 0; it < 8; it++) {
                int g = tid + it * GT;
                int grow = tn * 128 + (g >> 5);
                xr[it] = make_float4(0.f, 0.f, 0.f, 0.f);
                if (grow < M)
                    xr[it] = __ldg((const float4*)(X + (size_t)grow * IN_CH + (g & 31) * 4));
            }
        }

        float acc[2][4][4];
#pragma unroll
        for (int mt = 0; mt < 2; mt++)
#pragma unroll
            for (int nt = 0; nt < 4; nt++)
#pragma unroll
                for (int i = 0; i < 4; i++) acc[mt][nt][i] = 0.f;

        const uint32_t abase = sb + SM_A + buf * 65536;
#pragma unroll
        for (int p = 0; p < 3; p++) {
            const uint32_t Ab = abase + (p == 2 ? 32768 : 0);
            const uint32_t Bb = sb + (p == 1 ? SM_BLO : SM_BHI);
#pragma unroll
            for (int ks = 0; ks < 8; ks++) {
                const int k0 = ks * 16;
                uint32_t a[2][4];
#pragma unroll
                for (int mt = 0; mt < 2; mt++)
                    ldm_x4(a[mt], Ab + swz(mrow + mt * 16 + a_row, (k0 + a_koff) * 2));
                uint32_t b[2][4];
#pragma unroll
                for (int np = 0; np < 2; np++)
                    ldm_x4(b[np], Bb + swz(ncol + np * 16 + b_nr, (k0 + b_koff) * 2));
#pragma unroll
                for (int mt = 0; mt < 2; mt++)
#pragma unroll
                    for (int nt = 0; nt < 4; nt++)
                        mma_bf16(acc[mt][nt], a[mt], &b[nt >> 1][(nt & 1) * 2]);
            }
        }

        // epilogue: bias, fp16 store of h, fused alpha_s dot, running max
#pragma unroll
        for (int mt = 0; mt < 2; mt++) {
#pragma unroll
            for (int hh = 0; hh < 2; hh++) {
                const int r = mrow + mt * 16 + hh * 8 + rg;
                const int grow = t * 128 + r;
                const bool valid = grow < M;
                float ps = 0.f;
#pragma unroll
                for (int nt = 0; nt < 4; nt++) {
                    const int c0 = nt * 8 + 2 * q;
                    const int col = ncol + c0;
                    float v0 = acc[mt][nt][hh * 2 + 0] + s_bias[col];
                    float v1 = acc[mt][nt][hh * 2 + 1] + s_bias[col + 1];
                    if (valid) {
                        __half2 hv = __floats2half2_rn(v0, v1);
                        g_h16[(size_t)grow * 64 + wc * 16 + nt * 4 + q] =
                            *(const uint32_t*)&hv;
                    }
                    ps += v0 * s_att[wc * 64 + 32 + c0] + v1 * s_att[wc * 64 + 33 + c0];
                }
#pragma unroll
                for (int o = 1; o <= 2; o <<= 1)
                    ps += __shfl_xor_sync(0xffffffffu, ps, o);
                if (valid) {
                    lmax = fmaxf(lmax, ps);
                    if (q == 0) g_as[(size_t)grow * HEADS + wc] = ps;
                }
            }
        }

        if (tn < tiles) {
#pragma unroll
            for (int it = 0; it < 8; it++)
                store_a(smem, SM_A + (buf ^ 1) * 65536, tid + it * GT, xr[it]);
        }
        __syncthreads();
        buf ^= 1;
    }

    // CTA-wide max of alpha_s, one atomicMax per CTA
    unsigned int u = f2o(lmax);
#pragma unroll
    for (int o = 16; o; o >>= 1)
        u = max(u, __shfl_down_sync(0xffffffffu, u, o));
    unsigned int* sred = (unsigned int*)(smem + SM_RED);
    if (lane == 0) sred[wid] = u;
    __syncthreads();
    if (wid == 0) {
        u = (lane < 16) ? sred[lane] : 0u;
#pragma unroll
        for (int o = 8; o; o >>= 1)
            u = max(u, __shfl_down_sync(0xffffffffu, u, o));
        if (lane == 0) atomicMax(&g_maxs, u);
    }
}

// ---------------- per-node exp factors (in place) ----------------
__global__ __launch_bounds__(256) void nodeexp_kernel(int n) {
    int i = blockIdx.x * blockDim.x + threadIdx.x;
    if (i >= n) return;
    float Gs = o2f(g_maxs);
    g_as[i] = __expf(0.01f * (g_as[i] - Gs));
}

// ---------------- E1: decode, denominator red ----------------
__global__ __launch_bounds__(256) void edge_pass1(const void* __restrict__ idx, int E) {
    int i = blockIdx.x * blockDim.x + threadIdx.x;
    if (i >= E) return;
    int is64 = g_is64;
    int s = ldidx(idx, i, is64);
    int t = ldidx(idx, (long long)E + i, is64);
    g_edges[i] = make_int2(s, t);
    float4 w = __ldg((const float4*)(g_as + (size_t)s * HEADS));
    red_v4(g_den + (size_t)t * HEADS, w);
}

// ---------------- E3: weighted aggregation, 8 lanes per edge (fp16 h) ----------------
__global__ __launch_bounds__(256) void agg_kernel(int E, float* __restrict__ out) {
    int gtid = blockIdx.x * blockDim.x + threadIdx.x;
    int eid = gtid >> 3;
    if (eid >= E) return;
    int lg = gtid & 7;
    int2 st = __ldg((const int2*)&g_edges[eid]);
    float4 a = __ldg((const float4*)(g_as + (size_t)st.x * HEADS));
    float4 den = __ldg((const float4*)(g_den + (size_t)st.y * HEADS));
    float w0 = 0.25f * a.x / (den.x + EPS_F);
    float w1 = 0.25f * a.y / (den.y + EPS_F);
    float w2 = 0.25f * a.z / (den.z + EPS_F);
    float w3 = 0.25f * a.w / (den.w + EPS_F);
    const uint2* hp = (const uint2*)(g_h16 + (size_t)st.x * 64);
    uint2 u0 = __ldg(hp + 0 * 8 + lg);
    uint2 u1 = __ldg(hp + 1 * 8 + lg);
    uint2 u2 = __ldg(hp + 2 * 8 + lg);
    uint2 u3 = __ldg(hp + 3 * 8 + lg);
    float2 a01 = __half22float2(*(const __half2*)&u0.x);
    float2 a23 = __half22float2(*(const __half2*)&u0.y);
    float2 b01 = __half22float2(*(const __half2*)&u1.x);
    float2 b23 = __half22float2(*(const __half2*)&u1.y);
    float2 c01 = __half22float2(*(const __half2*)&u2.x);
    float2 c23 = __half22float2(*(const __half2*)&u2.y);
    float2 d01 = __half22float2(*(const __half2*)&u3.x);
    float2 d23 = __half22float2(*(const __half2*)&u3.y);
    float4 v;
    v.x = w0 * a01.x + w1 * b01.x + w2 * c01.x + w3 * d01.x;
    v.y = w0 * a01.y + w1 * b01.y + w2 * c01.y + w3 * d01.y;
    v.z = w0 * a23.x + w1 * b23.x + w2 * c23.x + w3 * d23.x;
    v.w = w0 * a23.y + w1 * b23.y + w2 * c23.y + w3 * d23.y;
    red_v4(out + (size_t)st.y * OUT_CH + lg * 4, v);
}

// ---------------- launch ----------------
extern "C" void kernel_launch(void* const* d_in, const int* in_sizes, int n_in,
                              void* d_out, int out_size) {
    const float* X    = (const float*)d_in[0];
    const void*  eidx = d_in[1];
    const float* W    = (const float*)d_in[2];
    const float* bias = (const float*)d_in[3];
    const float* att  = (const float*)d_in[4];
    float* out = (float*)d_out;

    int M = in_sizes[0] / IN_CH;          // nodes
    int E = in_sizes[1] / 2;              // edges
    int tiles = (M + 127) / 128;

    static int sms = 0;
    if (!sms) {
        cudaDeviceGetAttribute(&sms, cudaDevAttrMultiProcessorCount, 0);
        cudaFuncSetAttribute(gat_gemm_kernel,
                             cudaFuncAttributeMaxDynamicSharedMemorySize, SM_TOTAL);
    }
    int grid = sms < tiles ? sms : tiles;

    int nscan = E < 2048 ? E : 2048;
    prep_kernel<<<32, 256>>>(W, eidx, nscan, M);

    cudaMemsetAsync(d_out, 0, (size_t)out_size * sizeof(float));
    void* denPtr = nullptr;
    cudaGetSymbolAddress(&denPtr, g_den);
    cudaMemsetAsync(denPtr, 0, (size_t)M * HEADS * sizeof(float));

    gat_gemm_kernel<<<grid, GT, SM_TOTAL>>>(X, bias, att, M, tiles);

    nodeexp_kernel<<<(M * HEADS + 255) / 256, 256>>>(M * HEADS);

    edge_pass1<<<(E + 255) / 256, 256>>>(eidx, E);

    long long aggThreads = (long long)E * 8;
    agg_kernel<<<(unsigned)((aggThreads + 255) / 256), 256>>>(E, out);
}

// round 8
// speedup vs baseline: 1.1926x; 1.1926x over previous
#include <cuda_runtime.h>
#include <cuda_bf16.h>
#include <cuda_fp16.h>
#include <cstdint>

#define N_NODES_C 100000
#define N_EDGES_C 800000
#define HEADS 4
#define OUT_CH 32
#define IN_CH 128
#define HC 128            // HEADS*OUT_CH
#define EPS_F 1e-8f
#define TILE_M 64

// ---------------- device scratch (no allocs allowed) ----------------
__device__ __align__(16) uint32_t g_h16[(size_t)N_NODES_C * 64]; // h as half2 [N][64]
__device__ __align__(16) float g_as[N_NODES_C * HEADS];          // alpha_s -> exp factors
__device__ __align__(16) float g_den[N_NODES_C * HEADS];         // softmax denominators
__device__ __align__(16) int2  g_edges[N_EDGES_C];               // decoded (s,t)
__device__ unsigned int g_maxs;                                  // ordered-encoded max of as
__device__ int g_is64;                                           // edge index dtype flag
__device__ __align__(16) unsigned short g_Whi[HC * 128];         // W bf16 hi, swizzled
__device__ __align__(16) unsigned short g_Wlo[HC * 128];         // W bf16 lo, swizzled

// ordered float <-> uint mapping for atomicMax on floats
__device__ __forceinline__ unsigned int f2o(float f) {
    unsigned int b = __float_as_uint(f);
    return (b & 0x80000000u) ? ~b : (b | 0x80000000u);
}
__device__ __forceinline__ float o2f(unsigned int u) {
    unsigned int b = (u & 0x80000000u) ? (u ^ 0x80000000u) : ~u;
    return __uint_as_float(b);
}
__device__ __forceinline__ int ldidx(const void* p, long long i, int is64) {
    return is64 ? (int)((const long long*)p)[i] : ((const int*)p)[i];
}
__device__ __forceinline__ void red_v4(float* ptr, float4 v) {
    asm volatile("red.global.add.v4.f32 [%0], {%1,%2,%3,%4};"
                 :: "l"(ptr), "f"(v.x), "f"(v.y), "f"(v.z), "f"(v.w) : "memory");
}
__device__ __forceinline__ uint32_t smem_u32(const void* p) {
    uint32_t a;
    asm("{ .reg .u64 t; cvta.to.shared.u64 t, %1; cvt.u32.u64 %0, t; }" : "=r"(a) : "l"(p));
    return a;
}
__device__ __forceinline__ void cp_async16(uint32_t saddr, const void* gaddr) {
    asm volatile("cp.async.cg.shared.global [%0], [%1], 16;" :: "r"(saddr), "l"(gaddr));
}
__device__ __forceinline__ void ldm_x4(uint32_t* r, uint32_t addr) {
    asm volatile("ldmatrix.sync.aligned.m8n8.x4.shared.b16 {%0,%1,%2,%3}, [%4];"
                 : "=r"(r[0]), "=r"(r[1]), "=r"(r[2]), "=r"(r[3]) : "r"(addr));
}
__device__ __forceinline__ void mma_bf16(float* d, const uint32_t* a, const uint32_t* b) {
    asm volatile(
        "mma.sync.aligned.m16n8k16.row.col.f32.bf16.bf16.f32 "
        "{%0,%1,%2,%3}, {%4,%5,%6,%7}, {%8,%9}, {%0,%1,%2,%3};"
        : "+f"(d[0]), "+f"(d[1]), "+f"(d[2]), "+f"(d[3])
        : "r"(a[0]), "r"(a[1]), "r"(a[2]), "r"(a[3]), "r"(b[0]), "r"(b[1]));
}

// XOR swizzle: row stride 256B (128 bf16); flips 16B-chunk index bits with row&7
__device__ __forceinline__ uint32_t swz(int row, int kByte) {
    return (uint32_t)(row * 256 + (kByte ^ ((row & 7) << 4)));
}

// SMEM layout (bytes)
#define SM_BIAS 0
#define SM_ATT  512
#define SM_RED  1024
#define SM_AHI  1536
#define SM_ALO  (SM_AHI + 16384)
#define SM_BHI  (SM_ALO + 16384)
#define SM_BLO  (SM_BHI + 32768)
#define SM_TOTAL (SM_BLO + 32768)   // 99840

// ---------------- prep: W split + dtype detection ----------------
__global__ void prep_kernel(const float* __restrict__ W, const void* __restrict__ idx,
                            int nscan, int nnodes) {
    if (blockIdx.x == 0) {
        __shared__ int bad;
        if (threadIdx.x == 0) bad = 0;
        __syncthreads();
        const long long* p = (const long long*)idx;
        int ok = 1;
        for (int i = threadIdx.x; i < nscan; i += blockDim.x) {
            long long v = p[i];
            if (v < 0 || v >= (long long)nnodes) ok = 0;
        }
        if (!ok) atomicExch(&bad, 1);
        __syncthreads();
        if (threadIdx.x == 0) {
            g_is64 = bad ? 0 : 1;
            g_maxs = 0u;
        }
    }
    for (int idx2 = blockIdx.x * blockDim.x + threadIdx.x; idx2 < HC * IN_CH;
         idx2 += blockDim.x * gridDim.x) {
        int n = idx2 >> 7;
        int k = idx2 & 127;
        float w = W[idx2];
        __nv_bfloat16 hi = __float2bfloat16(w);
        float rem = w - __bfloat162float(hi);
        __nv_bfloat16 lo = __float2bfloat16(rem);
        uint32_t off = swz(n, k * 2) >> 1;
        g_Whi[off] = __bfloat16_as_ushort(hi);
        g_Wlo[off] = __bfloat16_as_ushort(lo);
    }
}

// ---------------- mma.sync GEMM + fused alpha_s epilogue + CTA max ----------------
// 64x128 tile per CTA, 2 CTAs/SM; 8 warps in 2x4 (row x col); warp tile 32x32.
__global__ void __launch_bounds__(256, 2)
gat_gemm_kernel(const float* __restrict__ X, const float* __restrict__ bias,
                const float* __restrict__ att, int M) {
    extern __shared__ char smem[];
    const uint32_t sb = smem_u32(smem);
    const int tid = threadIdx.x, lane = tid & 31, wid = tid >> 5;
    const int rowBase = blockIdx.x * TILE_M;

    if (tid < 128) ((float*)(smem + SM_BIAS))[tid] = bias[tid];
    ((float*)(smem + SM_ATT))[tid] = att[tid];

    // async copy of pre-swizzled W hi/lo (32 KB each)
    {
        const char* wh = (const char*)g_Whi;
        const char* wl = (const char*)g_Wlo;
#pragma unroll
        for (int it = 0; it < 8; it++) {
            int g = (tid + it * 256) * 16;
            cp_async16(sb + SM_BHI + g, wh + g);
            cp_async16(sb + SM_BLO + g, wl + g);
        }
        asm volatile("cp.async.commit_group;");
    }
    // A tile: load fp32 X, split into bf16 hi/lo, swizzled
#pragma unroll
    for (int it = 0; it < 8; it++) {
        int g = tid + it * 256;      // 0..2047
        int r = g >> 5;
        int c4 = (g & 31) * 4;
        int grow = rowBase + r;
        float4 v = make_float4(0.f, 0.f, 0.f, 0.f);
        if (grow < M) v = *(const float4*)(X + (size_t)grow * IN_CH + c4);
        __nv_bfloat16 h0 = __float2bfloat16(v.x);
        __nv_bfloat16 h1 = __float2bfloat16(v.y);
        __nv_bfloat16 h2 = __float2bfloat16(v.z);
        __nv_bfloat16 h3 = __float2bfloat16(v.w);
        __nv_bfloat16 l0 = __float2bfloat16(v.x - __bfloat162float(h0));
        __nv_bfloat16 l1 = __float2bfloat16(v.y - __bfloat162float(h1));
        __nv_bfloat16 l2 = __float2bfloat16(v.z - __bfloat162float(h2));
        __nv_bfloat16 l3 = __float2bfloat16(v.w - __bfloat162float(h3));
        uint32_t hiA = ((uint32_t)__bfloat16_as_ushort(h1) << 16) | __bfloat16_as_ushort(h0);
        uint32_t hiB = ((uint32_t)__bfloat16_as_ushort(h3) << 16) | __bfloat16_as_ushort(h2);
        uint32_t loA = ((uint32_t)__bfloat16_as_ushort(l1) << 16) | __bfloat16_as_ushort(l0);
        uint32_t loB = ((uint32_t)__bfloat16_as_ushort(l3) << 16) | __bfloat16_as_ushort(l2);
        uint32_t off = swz(r, c4 * 2);
        *(uint2*)(smem + SM_AHI + off) = make_uint2(hiA, hiB);
        *(uint2*)(smem + SM_ALO + off) = make_uint2(loA, loB);
    }
    asm volatile("cp.async.wait_group 0;" ::: "memory");
    __syncthreads();

    const int wr = wid & 1, wc = wid >> 1;
    const int mrow = wr * 32;      // warp row base (32 rows)
    const int ncol = wc * 32;      // warp col base = head wc

    float acc[2][4][4];
#pragma unroll
    for (int mt = 0; mt < 2; mt++)
#pragma unroll
        for (int nt = 0; nt < 4; nt++)
#pragma unroll
            for (int i = 0; i < 4; i++) acc[mt][nt][i] = 0.f;

    const int a_row = (lane & 15);
    const int a_koff = (lane >> 4) * 8;
    const int b_nr = (lane & 7) + ((lane >> 4) & 1) * 8;
    const int b_koff = ((lane >> 3) & 1) * 8;

#pragma unroll
    for (int p = 0; p < 3; p++) {
        const uint32_t Ab = sb + (p == 2 ? SM_ALO : SM_AHI);
        const uint32_t Bb = sb + (p == 1 ? SM_BLO : SM_BHI);
#pragma unroll
        for (int ks = 0; ks < 8; ks++) {
            const int k0 = ks * 16;
            uint32_t a[2][4];
#pragma unroll
            for (int mt = 0; mt < 2; mt++) {
                int row = mrow + mt * 16 + a_row;
                ldm_x4(a[mt], Ab + swz(row, (k0 + a_koff) * 2));
            }
            uint32_t b[2][4];
#pragma unroll
            for (int np = 0; np < 2; np++) {
                int row = ncol + np * 16 + b_nr;
                ldm_x4(b[np], Bb + swz(row, (k0 + b_koff) * 2));
            }
#pragma unroll
            for (int mt = 0; mt < 2; mt++)
#pragma unroll
                for (int nt = 0; nt < 4; nt++)
                    mma_bf16(acc[mt][nt], a[mt], &b[nt >> 1][(nt & 1) * 2]);
        }
    }

    // epilogue: bias, fp16 store of h, fused alpha_s dot (head = wc), CTA max
    const float* s_bias = (const float*)(smem + SM_BIAS);
    const float* s_att = (const float*)(smem + SM_ATT);
    const int q = lane & 3, rg = lane >> 2;
    float lmax = -3.4e38f;

#pragma unroll
    for (int mt = 0; mt < 2; mt++) {
#pragma unroll
        for (int hh = 0; hh < 2; hh++) {
            const int r = mrow + mt * 16 + hh * 8 + rg;
            const int grow = rowBase + r;
            const bool valid = grow < M;
            float ps = 0.f;
#pragma unroll
            for (int nt = 0; nt < 4; nt++) {
                const int c0 = nt * 8 + 2 * q;          // 0..31 within head
                const int col = ncol + c0;
                float v0 = acc[mt][nt][hh * 2 + 0] + s_bias[col];
                float v1 = acc[mt][nt][hh * 2 + 1] + s_bias[col + 1];
                if (valid) {
                    __half2 hv = __floats2half2_rn(v0, v1);
                    g_h16[(size_t)grow * 64 + wc * 16 + nt * 4 + q] = *(const uint32_t*)&hv;
                }
                ps += v0 * s_att[wc * 64 + 32 + c0] + v1 * s_att[wc * 64 + 33 + c0];
            }
#pragma unroll
            for (int o = 1; o <= 2; o <<= 1)
                ps += __shfl_xor_sync(0xffffffffu, ps, o);
            if (valid) {
                lmax = fmaxf(lmax, ps);
                if (q == 0) g_as[(size_t)grow * HEADS + wc] = ps;
            }
        }
    }
    // CTA-wide max of alpha_s, one atomicMax per CTA
    unsigned int u = f2o(lmax);
#pragma unroll
    for (int o = 16; o; o >>= 1)
        u = max(u, __shfl_down_sync(0xffffffffu, u, o));
    unsigned int* sred = (unsigned int*)(smem + SM_RED);
    if (lane == 0) sred[wid] = u;
    __syncthreads();
    if (wid == 0) {
        u = (lane < 8) ? sred[lane] : 0u;
#pragma unroll
        for (int o = 4; o; o >>= 1)
            u = max(u, __shfl_down_sync(0xffffffffu, u, o));
        if (lane == 0) atomicMax(&g_maxs, u);
    }
}

// ---------------- per-node exp factors (in place) ----------------
__global__ __launch_bounds__(256) void nodeexp_kernel(int n) {
    int i = blockIdx.x * blockDim.x + threadIdx.x;
    if (i >= n) return;
    float Gs = o2f(g_maxs);
    g_as[i] = __expf(0.01f * (g_as[i] - Gs));
}

// ---------------- E1: decode, denominator red ----------------
__global__ __launch_bounds__(256) void edge_pass1(const void* __restrict__ idx, int E) {
    int i = blockIdx.x * blockDim.x + threadIdx.x;
    if (i >= E) return;
    int is64 = g_is64;
    int s = ldidx(idx, i, is64);
    int t = ldidx(idx, (long long)E + i, is64);
    g_edges[i] = make_int2(s, t);
    float4 w = __ldg((const float4*)(g_as + (size_t)s * HEADS));
    red_v4(g_den + (size_t)t * HEADS, w);
}

// ---------------- E3: weighted aggregation, 8 lanes per edge (fp16 h) ----------------
__global__ __launch_bounds__(256) void agg_kernel(int E, float* __restrict__ out) {
    int gtid = blockIdx.x * blockDim.x + threadIdx.x;
    int eid = gtid >> 3;
    if (eid >= E) return;
    int lg = gtid & 7;
    int2 st = __ldg((const int2*)&g_edges[eid]);
    float4 a = __ldg((const float4*)(g_as + (size_t)st.x * HEADS));
    float4 den = __ldg((const float4*)(g_den + (size_t)st.y * HEADS));
    float w0 = 0.25f * a.x / (den.x + EPS_F);
    float w1 = 0.25f * a.y / (den.y + EPS_F);
    float w2 = 0.25f * a.z / (den.z + EPS_F);
    float w3 = 0.25f * a.w / (den.w + EPS_F);
    const uint2* hp = (const uint2*)(g_h16 + (size_t)st.x * 64);
    uint2 u0 = __ldg(hp + 0 * 8 + lg);
    uint2 u1 = __ldg(hp + 1 * 8 + lg);
    uint2 u2 = __ldg(hp + 2 * 8 + lg);
    uint2 u3 = __ldg(hp + 3 * 8 + lg);
    float2 a01 = __half22float2(*(const __half2*)&u0.x);
    float2 a23 = __half22float2(*(const __half2*)&u0.y);
    float2 b01 = __half22float2(*(const __half2*)&u1.x);
    float2 b23 = __half22float2(*(const __half2*)&u1.y);
    float2 c01 = __half22float2(*(const __half2*)&u2.x);
    float2 c23 = __half22float2(*(const __half2*)&u2.y);
    float2 d01 = __half22float2(*(const __half2*)&u3.x);
    float2 d23 = __half22float2(*(const __half2*)&u3.y);
    float4 v;
    v.x = w0 * a01.x + w1 * b01.x + w2 * c01.x + w3 * d01.x;
    v.y = w0 * a01.y + w1 * b01.y + w2 * c01.y + w3 * d01.y;
    v.z = w0 * a23.x + w1 * b23.x + w2 * c23.x + w3 * d23.x;
    v.w = w0 * a23.y + w1 * b23.y + w2 * c23.y + w3 * d23.y;
    red_v4(out + (size_t)st.y * OUT_CH + lg * 4, v);
}

// ---------------- launch ----------------
extern "C" void kernel_launch(void* const* d_in, const int* in_sizes, int n_in,
                              void* d_out, int out_size) {
    const float* X    = (const float*)d_in[0];
    const void*  eidx = d_in[1];
    const float* W    = (const float*)d_in[2];
    const float* bias = (const float*)d_in[3];
    const float* att  = (const float*)d_in[4];
    float* out = (float*)d_out;

    int M = in_sizes[0] / IN_CH;          // nodes
    int E = in_sizes[1] / 2;              // edges

    cudaFuncSetAttribute(gat_gemm_kernel,
                         cudaFuncAttributeMaxDynamicSharedMemorySize, SM_TOTAL);

    int nscan = E < 2048 ? E : 2048;
    prep_kernel<<<32, 256>>>(W, eidx, nscan, M);

    cudaMemsetAsync(d_out, 0, (size_t)out_size * sizeof(float));
    void* denPtr = nullptr;
    cudaGetSymbolAddress(&denPtr, g_den);
    cudaMemsetAsync(denPtr, 0, (size_t)M * HEADS * sizeof(float));

    gat_gemm_kernel<<<(M + TILE_M - 1) / TILE_M, 256, SM_TOTAL>>>(X, bias, att, M);

    nodeexp_kernel<<<(M * HEADS + 255) / 256, 256>>>(M * HEADS);

    edge_pass1<<<(E + 255) / 256, 256>>>(eidx, E);

    long long aggThreads = (long long)E * 8;
    agg_kernel<<<(unsigned)((aggThreads + 255) / 256), 256>>>(E, out);
}

// round 9
// speedup vs baseline: 1.2390x; 1.0389x over previous
#include <cuda_runtime.h>
#include <cuda_bf16.h>
#include <cuda_fp16.h>
#include <cstdint>

#define N_NODES_C 100000
#define N_EDGES_C 800000
#define HEADS 4
#define OUT_CH 32
#define IN_CH 128
#define HC 128            // HEADS*OUT_CH
#define EPS_F 1e-8f
#define TILE_M 64

// ---------------- device scratch (no allocs allowed) ----------------
__device__ __align__(16) uint32_t g_h16[(size_t)N_NODES_C * 64]; // h as half2 [N][64]
__device__ __align__(16) float g_as[N_NODES_C * HEADS];          // exp(0.01*alpha_s)
__device__ __align__(16) float g_den[N_NODES_C * HEADS];         // softmax denominators
__device__ __align__(16) int2  g_edges[N_EDGES_C];               // decoded (s,t)
__device__ int g_is64;                                           // edge index dtype flag
__device__ __align__(16) unsigned short g_Whi[HC * 128];         // W bf16 hi, swizzled
__device__ __align__(16) unsigned short g_Wlo[HC * 128];         // W bf16 lo, swizzled

__device__ __forceinline__ int ldidx(const void* p, long long i, int is64) {
    return is64 ? (int)((const long long*)p)[i] : ((const int*)p)[i];
}
__device__ __forceinline__ void red_v4(float* ptr, float4 v) {
    asm volatile("red.global.add.v4.f32 [%0], {%1,%2,%3,%4};"
                 :: "l"(ptr), "f"(v.x), "f"(v.y), "f"(v.z), "f"(v.w) : "memory");
}
__device__ __forceinline__ uint32_t smem_u32(const void* p) {
    uint32_t a;
    asm("{ .reg .u64 t; cvta.to.shared.u64 t, %1; cvt.u32.u64 %0, t; }" : "=r"(a) : "l"(p));
    return a;
}
__device__ __forceinline__ void cp_async16(uint32_t saddr, const void* gaddr) {
    asm volatile("cp.async.cg.shared.global [%0], [%1], 16;" :: "r"(saddr), "l"(gaddr));
}
__device__ __forceinline__ void ldm_x4(uint32_t* r, uint32_t addr) {
    asm volatile("ldmatrix.sync.aligned.m8n8.x4.shared.b16 {%0,%1,%2,%3}, [%4];"
                 : "=r"(r[0]), "=r"(r[1]), "=r"(r[2]), "=r"(r[3]) : "r"(addr));
}
__device__ __forceinline__ void mma_bf16(float* d, const uint32_t* a, const uint32_t* b) {
    asm volatile(
        "mma.sync.aligned.m16n8k16.row.col.f32.bf16.bf16.f32 "
        "{%0,%1,%2,%3}, {%4,%5,%6,%7}, {%8,%9}, {%0,%1,%2,%3};"
        : "+f"(d[0]), "+f"(d[1]), "+f"(d[2]), "+f"(d[3])
        : "r"(a[0]), "r"(a[1]), "r"(a[2]), "r"(a[3]), "r"(b[0]), "r"(b[1]));
}
// XOR swizzle: row stride 256B (128 bf16)
__device__ __forceinline__ uint32_t swz(int row, int kByte) {
    return (uint32_t)(row * 256 + (kByte ^ ((row & 7) << 4)));
}

// SMEM layout (bytes)
#define SM_BIAS 0
#define SM_ATT  512
#define SM_AHI  1536
#define SM_ALO  (SM_AHI + 16384)
#define SM_BHI  (SM_ALO + 16384)
#define SM_BLO  (SM_BHI + 32768)
#define SM_TOTAL (SM_BLO + 32768)   // 99840

// ---------------- prep: W split + dtype detection ----------------
__global__ void prep_kernel(const float* __restrict__ W, const void* __restrict__ idx,
                            int nscan, int nnodes) {
    if (blockIdx.x == 0) {
        __shared__ int bad;
        if (threadIdx.x == 0) bad = 0;
        __syncthreads();
        const long long* p = (const long long*)idx;
        int ok = 1;
        for (int i = threadIdx.x; i < nscan; i += blockDim.x) {
            long long v = p[i];
            if (v < 0 || v >= (long long)nnodes) ok = 0;
        }
        if (!ok) atomicExch(&bad, 1);
        __syncthreads();
        if (threadIdx.x == 0) g_is64 = bad ? 0 : 1;
    }
    for (int idx2 = blockIdx.x * blockDim.x + threadIdx.x; idx2 < HC * IN_CH;
         idx2 += blockDim.x * gridDim.x) {
        int n = idx2 >> 7;
        int k = idx2 & 127;
        float w = W[idx2];
        __nv_bfloat16 hi = __float2bfloat16(w);
        float rem = w - __bfloat162float(hi);
        __nv_bfloat16 lo = __float2bfloat16(rem);
        uint32_t off = swz(n, k * 2) >> 1;
        g_Whi[off] = __bfloat16_as_ushort(hi);
        g_Wlo[off] = __bfloat16_as_ushort(lo);
    }
}

// ---------------- edge decode (overlaps with GEMM on side stream) ----------------
__global__ __launch_bounds__(256) void decode_kernel(const void* __restrict__ idx, int E) {
    int i = blockIdx.x * blockDim.x + threadIdx.x;
    if (i >= E) return;
    int is64 = g_is64;
    int s = ldidx(idx, i, is64);
    int t = ldidx(idx, (long long)E + i, is64);
    g_edges[i] = make_int2(s, t);
}

// ---------------- mma.sync GEMM + fused exp(alpha_s) epilogue ----------------
// 64x128 tile per CTA, 2 CTAs/SM; 8 warps in 2x4; warp tile 32x32.
__global__ void __launch_bounds__(256, 2)
gat_gemm_kernel(const float* __restrict__ X, const float* __restrict__ bias,
                const float* __restrict__ att, int M) {
    extern __shared__ char smem[];
    const uint32_t sb = smem_u32(smem);
    const int tid = threadIdx.x, lane = tid & 31, wid = tid >> 5;
    const int rowBase = blockIdx.x * TILE_M;

    if (tid < 128) ((float*)(smem + SM_BIAS))[tid] = bias[tid];
    ((float*)(smem + SM_ATT))[tid] = att[tid];

    // async copy of pre-swizzled W hi/lo (32 KB each)
    {
        const char* wh = (const char*)g_Whi;
        const char* wl = (const char*)g_Wlo;
#pragma unroll
        for (int it = 0; it < 8; it++) {
            int g = (tid + it * 256) * 16;
            cp_async16(sb + SM_BHI + g, wh + g);
            cp_async16(sb + SM_BLO + g, wl + g);
        }
        asm volatile("cp.async.commit_group;");
    }
    // A tile: load fp32 X, split into bf16 hi/lo, swizzled
#pragma unroll
    for (int it = 0; it < 8; it++) {
        int g = tid + it * 256;      // 0..2047
        int r = g >> 5;
        int c4 = (g & 31) * 4;
        int grow = rowBase + r;
        float4 v = make_float4(0.f, 0.f, 0.f, 0.f);
        if (grow < M) v = __ldg((const float4*)(X + (size_t)grow * IN_CH + c4));
        __nv_bfloat16 h0 = __float2bfloat16(v.x);
        __nv_bfloat16 h1 = __float2bfloat16(v.y);
        __nv_bfloat16 h2 = __float2bfloat16(v.z);
        __nv_bfloat16 h3 = __float2bfloat16(v.w);
        __nv_bfloat16 l0 = __float2bfloat16(v.x - __bfloat162float(h0));
        __nv_bfloat16 l1 = __float2bfloat16(v.y - __bfloat162float(h1));
        __nv_bfloat16 l2 = __float2bfloat16(v.z - __bfloat162float(h2));
        __nv_bfloat16 l3 = __float2bfloat16(v.w - __bfloat162float(h3));
        uint32_t hiA = ((uint32_t)__bfloat16_as_ushort(h1) << 16) | __bfloat16_as_ushort(h0);
        uint32_t hiB = ((uint32_t)__bfloat16_as_ushort(h3) << 16) | __bfloat16_as_ushort(h2);
        uint32_t loA = ((uint32_t)__bfloat16_as_ushort(l1) << 16) | __bfloat16_as_ushort(l0);
        uint32_t loB = ((uint32_t)__bfloat16_as_ushort(l3) << 16) | __bfloat16_as_ushort(l2);
        uint32_t off = swz(r, c4 * 2);
        *(uint2*)(smem + SM_AHI + off) = make_uint2(hiA, hiB);
        *(uint2*)(smem + SM_ALO + off) = make_uint2(loA, loB);
    }
    asm volatile("cp.async.wait_group 0;" ::: "memory");
    __syncthreads();

    const int wr = wid & 1, wc = wid >> 1;
    const int mrow = wr * 32;
    const int ncol = wc * 32;

    float acc[2][4][4];
#pragma unroll
    for (int mt = 0; mt < 2; mt++)
#pragma unroll
        for (int nt = 0; nt < 4; nt++)
#pragma unroll
            for (int i = 0; i < 4; i++) acc[mt][nt][i] = 0.f;

    const int a_row = (lane & 15);
    const int a_koff = (lane >> 4) * 8;
    const int b_nr = (lane & 7) + ((lane >> 4) & 1) * 8;
    const int b_koff = ((lane >> 3) & 1) * 8;

#pragma unroll
    for (int p = 0; p < 3; p++) {
        const uint32_t Ab = sb + (p == 2 ? SM_ALO : SM_AHI);
        const uint32_t Bb = sb + (p == 1 ? SM_BLO : SM_BHI);
#pragma unroll
        for (int ks = 0; ks < 8; ks++) {
            const int k0 = ks * 16;
            uint32_t a[2][4];
#pragma unroll
            for (int mt = 0; mt < 2; mt++) {
                int row = mrow + mt * 16 + a_row;
                ldm_x4(a[mt], Ab + swz(row, (k0 + a_koff) * 2));
            }
            uint32_t b[2][4];
#pragma unroll
            for (int np = 0; np < 2; np++) {
                int row = ncol + np * 16 + b_nr;
                ldm_x4(b[np], Bb + swz(row, (k0 + b_koff) * 2));
            }
#pragma unroll
            for (int mt = 0; mt < 2; mt++)
#pragma unroll
                for (int nt = 0; nt < 4; nt++)
                    mma_bf16(acc[mt][nt], a[mt], &b[nt >> 1][(nt & 1) * 2]);
        }
    }

    // epilogue: bias, fp16 store of h, fused exp(0.01*alpha_s) (head = wc)
    const float* s_bias = (const float*)(smem + SM_BIAS);
    const float* s_att = (const float*)(smem + SM_ATT);
    const int q = lane & 3, rg = lane >> 2;

#pragma unroll
    for (int mt = 0; mt < 2; mt++) {
#pragma unroll
        for (int hh = 0; hh < 2; hh++) {
            const int r = mrow + mt * 16 + hh * 8 + rg;
            const int grow = rowBase + r;
            const bool valid = grow < M;
            float ps = 0.f;
#pragma unroll
            for (int nt = 0; nt < 4; nt++) {
                const int c0 = nt * 8 + 2 * q;
                const int col = ncol + c0;
                float v0 = acc[mt][nt][hh * 2 + 0] + s_bias[col];
                float v1 = acc[mt][nt][hh * 2 + 1] + s_bias[col + 1];
                if (valid) {
                    __half2 hv = __floats2half2_rn(v0, v1);
                    g_h16[(size_t)grow * 64 + wc * 16 + nt * 4 + q] = *(const uint32_t*)&hv;
                }
                ps += v0 * s_att[wc * 64 + 32 + c0] + v1 * s_att[wc * 64 + 33 + c0];
            }
#pragma unroll
            for (int o = 1; o <= 2; o <<= 1)
                ps += __shfl_xor_sync(0xffffffffu, ps, o);
            if (q == 0 && valid)
                g_as[(size_t)grow * HEADS + wc] = __expf(0.01f * ps);
        }
    }
}

// ---------------- E1: denominator red (pre-decoded edges) ----------------
__global__ __launch_bounds__(256) void edge_pass1(int E) {
    int i = blockIdx.x * blockDim.x + threadIdx.x;
    if (i >= E) return;
    int2 st = __ldg((const int2*)&g_edges[i]);
    float4 w = __ldg((const float4*)(g_as + (size_t)st.x * HEADS));
    red_v4(g_den + (size_t)st.y * HEADS, w);
}

// ---------------- E3: weighted aggregation, 8 lanes per edge (fp16 h) ----------------
__global__ __launch_bounds__(256) void agg_kernel(int E, float* __restrict__ out) {
    int gtid = blockIdx.x * blockDim.x + threadIdx.x;
    int eid = gtid >> 3;
    if (eid >= E) return;
    int lg = gtid & 7;
    int2 st = __ldg((const int2*)&g_edges[eid]);
    float4 a = __ldg((const float4*)(g_as + (size_t)st.x * HEADS));
    float4 den = __ldg((const float4*)(g_den + (size_t)st.y * HEADS));
    float w0 = 0.25f * a.x / (den.x + EPS_F);
    float w1 = 0.25f * a.y / (den.y + EPS_F);
    float w2 = 0.25f * a.z / (den.z + EPS_F);
    float w3 = 0.25f * a.w / (den.w + EPS_F);
    const uint2* hp = (const uint2*)(g_h16 + (size_t)st.x * 64);
    uint2 u0 = __ldg(hp + 0 * 8 + lg);
    uint2 u1 = __ldg(hp + 1 * 8 + lg);
    uint2 u2 = __ldg(hp + 2 * 8 + lg);
    uint2 u3 = __ldg(hp + 3 * 8 + lg);
    float2 a01 = __half22float2(*(const __half2*)&u0.x);
    float2 a23 = __half22float2(*(const __half2*)&u0.y);
    float2 b01 = __half22float2(*(const __half2*)&u1.x);
    float2 b23 = __half22float2(*(const __half2*)&u1.y);
    float2 c01 = __half22float2(*(const __half2*)&u2.x);
    float2 c23 = __half22float2(*(const __half2*)&u2.y);
    float2 d01 = __half22float2(*(const __half2*)&u3.x);
    float2 d23 = __half22float2(*(const __half2*)&u3.y);
    float4 v;
    v.x = w0 * a01.x + w1 * b01.x + w2 * c01.x + w3 * d01.x;
    v.y = w0 * a01.y + w1 * b01.y + w2 * c01.y + w3 * d01.y;
    v.z = w0 * a23.x + w1 * b23.x + w2 * c23.x + w3 * d23.x;
    v.w = w0 * a23.y + w1 * b23.y + w2 * c23.y + w3 * d23.y;
    red_v4(out + (size_t)st.y * OUT_CH + lg * 4, v);
}

// ---------------- launch ----------------
extern "C" void kernel_launch(void* const* d_in, const int* in_sizes, int n_in,
                              void* d_out, int out_size) {
    const float* X    = (const float*)d_in[0];
    const void*  eidx = d_in[1];
    const float* W    = (const float*)d_in[2];
    const float* bias = (const float*)d_in[3];
    const float* att  = (const float*)d_in[4];
    float* out = (float*)d_out;

    int M = in_sizes[0] / IN_CH;          // nodes
    int E = in_sizes[1] / 2;              // edges

    static cudaStream_t s1 = nullptr;
    static cudaEvent_t evFork = nullptr, evJoin = nullptr;
    static void* denPtr = nullptr;
    if (!s1) {
        cudaStreamCreateWithFlags(&s1, cudaStreamNonBlocking);
        cudaEventCreateWithFlags(&evFork, cudaEventDisableTiming);
        cudaEventCreateWithFlags(&evJoin, cudaEventDisableTiming);
        cudaGetSymbolAddress(&denPtr, g_den);
        cudaFuncSetAttribute(gat_gemm_kernel,
                             cudaFuncAttributeMaxDynamicSharedMemorySize, SM_TOTAL);
    }

    int nscan = E < 2048 ? E : 2048;
    prep_kernel<<<32, 256>>>(W, eidx, nscan, M);

    // fork: decode + memsets run on s1 concurrently with the GEMM on stream 0
    cudaEventRecord(evFork, 0);
    cudaStreamWaitEvent(s1, evFork, 0);
    decode_kernel<<<(E + 255) / 256, 256, 0, s1>>>(eidx, E);
    cudaMemsetAsync(d_out, 0, (size_t)out_size * sizeof(float), s1);
    cudaMemsetAsync(denPtr, 0, (size_t)M * HEADS * sizeof(float), s1);
    cudaEventRecord(evJoin, s1);

    gat_gemm_kernel<<<(M + TILE_M - 1) / TILE_M, 256, SM_TOTAL>>>(X, bias, att, M);

    // join before the edge phase
    cudaStreamWaitEvent(0, evJoin, 0);

    edge_pass1<<<(E + 255) / 256, 256>>>(E);

    long long aggThreads = (long long)E * 8;
    agg_kernel<<<(unsigned)((aggThreads + 255) / 256), 256>>>(E, out);
}